// round 7
// baseline (speedup 1.0000x reference)
#include <cuda_runtime.h>
#include <cstdint>

#define NNODES 8192
#define FEATD  1024
#define HDIM   512
#define GDIM   (5*HDIM)
#define NCTA   64
#define WPC    8                 // warps per CTA; warp w owns unit cta*8+w
#define NTHR   (WPC*32)
#define NCOPIES 8                // mailbox replicas; 8 consumer CTAs per copy
#define SENT   0xFFC0DEADu      // sentinel for g_C only (general-tree path)

// Scratch (static __device__ arrays: allocation-free per harness rules)
__device__ float g_xgb[(size_t)NNODES * GDIM];   // Wx·x + bx + bh   [N,5H]
__device__ float g_pxb[(size_t)NNODES * HDIM];   // Wpx·x + bpx      [N,H]
__device__ float g_C[(size_t)NNODES * HDIM];     // cell states      [N,H]
// Tagged mailbox: [step parity][copy][unit] = {h value bits, tag = t+1}
__device__ uint2 g_mbox[2][NCOPIES][HDIM];       // 64 KB

__device__ __forceinline__ float sigm(float x) {
    return 1.0f / (1.0f + __expf(-x));
}
__device__ __forceinline__ float tanhfast(float x) {
    return 1.0f - 2.0f / (__expf(2.0f * x) + 1.0f);
}
__device__ __forceinline__ uint4 ld_volatile_u4(const void* p) {
    uint4 v;
    asm volatile("ld.volatile.global.v4.b32 {%0,%1,%2,%3}, [%4];"
                 : "=r"(v.x), "=r"(v.y), "=r"(v.z), "=r"(v.w) : "l"(p) : "memory");
    return v;
}
__device__ __forceinline__ float ld_volatile_f(const float* p) {
    float v;
    asm volatile("ld.volatile.global.f32 %0, [%1];" : "=f"(v) : "l"(p) : "memory");
    return v;
}
__device__ __forceinline__ void st_v2_u32(void* p, unsigned a, unsigned b) {
    asm volatile("st.global.v2.b32 [%0], {%1,%2};" :: "l"(p), "r"(a), "r"(b) : "memory");
}
__device__ __forceinline__ float desent(float v) {   // g_C values only
    return (__float_as_uint(v) == SENT) ? __uint_as_float(SENT ^ 1u) : v;
}

// ---------------------------------------------------------------------------
// Per-launch reset: zero mailbox tags (64KB) + sentinel-poison g_C (16MB).
// ---------------------------------------------------------------------------
#define MBOX_U4   (2 * NCOPIES * HDIM / 2)        // 4096 uint4
#define GC_F4     (NNODES * HDIM / 4)             // 1048576 float4
__global__ void poison_kernel(float4* __restrict__ gc) {
    int i = blockIdx.x * blockDim.x + threadIdx.x;
    if (i < MBOX_U4) {
        ((uint4*)g_mbox)[i] = make_uint4(0u, 0u, 0u, 0u);
    }
    int j = i - MBOX_U4;
    if (j >= 0 && j < GC_F4) {
        float f = __uint_as_float(SENT);
        gc[j] = make_float4(f, f, f, f);
    }
}

// ---------------------------------------------------------------------------
// Batched precompute GEMM:  C[M,N] = A[M,K] * B[N,K]^T + b1[N] (+ b2[N])
// 128x128x8 SMEM-tiled fp32, 256 threads, 8x8 per-thread tile.
// ---------------------------------------------------------------------------
__global__ __launch_bounds__(256) void sgemm_bt_bias(
    const float* __restrict__ A, const float* __restrict__ B,
    const float* __restrict__ b1, const float* __restrict__ b2,
    float* __restrict__ C, int M, int N, int K)
{
    const int BM = 128, BN = 128;
    __shared__ float As[8][BM + 4];
    __shared__ float Bs[8][BN + 4];

    const int tid = threadIdx.x;
    const int bxi = blockIdx.x, byi = blockIdx.y;
    const int loadRow = tid >> 1;
    const int loadCol = (tid & 1) << 2;

    const float* Ab = A + (size_t)byi * BM * K;
    const float* Bb = B + (size_t)bxi * BN * K;

    const int ty = tid >> 4;
    const int tx = tid & 15;

    float acc[8][8];
#pragma unroll
    for (int i = 0; i < 8; i++)
#pragma unroll
        for (int j = 0; j < 8; j++) acc[i][j] = 0.0f;

    for (int k0 = 0; k0 < K; k0 += 8) {
        float4 av = *(const float4*)(Ab + (size_t)loadRow * K + k0 + loadCol);
        float4 bv = *(const float4*)(Bb + (size_t)loadRow * K + k0 + loadCol);
        As[loadCol + 0][loadRow] = av.x;
        As[loadCol + 1][loadRow] = av.y;
        As[loadCol + 2][loadRow] = av.z;
        As[loadCol + 3][loadRow] = av.w;
        Bs[loadCol + 0][loadRow] = bv.x;
        Bs[loadCol + 1][loadRow] = bv.y;
        Bs[loadCol + 2][loadRow] = bv.z;
        Bs[loadCol + 3][loadRow] = bv.w;
        __syncthreads();

#pragma unroll
        for (int k = 0; k < 8; k++) {
            float ar[8], br[8];
#pragma unroll
            for (int i = 0; i < 8; i++) ar[i] = As[k][ty * 8 + i];
#pragma unroll
            for (int j = 0; j < 8; j++) br[j] = Bs[k][tx * 8 + j];
#pragma unroll
            for (int i = 0; i < 8; i++)
#pragma unroll
                for (int j = 0; j < 8; j++)
                    acc[i][j] = fmaf(ar[i], br[j], acc[i][j]);
        }
        __syncthreads();
    }

#pragma unroll
    for (int i = 0; i < 8; i++) {
        int m = byi * BM + ty * 8 + i;
        int nbase = bxi * BN + tx * 8;
        float v[8];
#pragma unroll
        for (int j = 0; j < 8; j++) {
            v[j] = acc[i][j] + b1[nbase + j];
            if (b2) v[j] += b2[nbase + j];
        }
        float4* out = (float4*)(C + (size_t)m * N + nbase);
        out[0] = make_float4(v[0], v[1], v[2], v[3]);
        out[1] = make_float4(v[4], v[5], v[6], v[7]);
    }
}

// ---------------------------------------------------------------------------
// Persistent serial recurrence. 64 CTAs x 256 threads; warp w owns unit
// cta*8+w (80 weight regs). Publish: tagged {value, t+1} pairs fanned out to
// 8 mailbox copies (lanes 0..7, one 8B store each). Consume: each CTA polls
// ONLY its copy (8 readers/line -> latency-bound, not throttled); all 8 warps
// poll 64 units each, share via SMEM. Tag-match == valid; no fences needed.
// ---------------------------------------------------------------------------
__global__ __launch_bounds__(NTHR, 1) void treelstm_seq_kernel(
    const float* __restrict__ Wh, const int* __restrict__ parents,
    float* __restrict__ Hout)
{
    __shared__ float s_h[HDIM];      // assembled h[parent] (2KB)

    const int cta  = blockIdx.x;
    const int w    = threadIdx.x >> 5;
    const int lane = threadIdx.x & 31;
    const int unit = cta * WPC + w;
    const int copy = cta >> 3;       // 8 CTAs share a mailbox copy

    // Pin this unit's 5 Wh rows in registers: lane covers k = 4*lane + 128*c.
    float4 wv[5][4];
#pragma unroll
    for (int g = 0; g < 5; g++) {
        const float* wrow = Wh + (size_t)(g * HDIM + unit) * HDIM + 4 * lane;
#pragma unroll
        for (int c = 0; c < 4; c++)
            wv[g][c] = *(const float4*)(wrow + 128 * c);
    }

    // Node-0 static terms, loaded by ALL lanes (lane-uniform broadcast loads)
    float xg[5], px;
#pragma unroll
    for (int g = 0; g < 5; g++) xg[g] = g_xgb[(size_t)(g * HDIM + unit)];
    px = g_pxb[unit];

    float c_last = 0.0f;
    int p = parents[0];

    for (int t = 0; t < NNODES; t++) {
        const int p_next = (t + 1 < NNODES) ? parents[t + 1] : 0;

        float4 h0, h1, h2, h3;
        if (p >= 0) {
            // --- poll own copy: warp w handles units [64w, 64w+64) ---
            {
                const unsigned expect = (unsigned)(p + 1);
                const uint2* mp = &g_mbox[p & 1][copy][64 * w + 2 * lane];
                uint4 v;
                for (;;) {
                    v = ld_volatile_u4(mp);
                    bool ok = (v.y == expect) & (v.w == expect);
                    if (__all_sync(0xffffffffu, ok)) break;
                }
                *(float2*)&s_h[64 * w + 2 * lane] =
                    make_float2(__uint_as_float(v.x), __uint_as_float(v.z));
            }
            __syncthreads();                   // s_h fully assembled
            h0 = *(const float4*)&s_h[4 * lane +   0];
            h1 = *(const float4*)&s_h[4 * lane + 128];
            h2 = *(const float4*)&s_h[4 * lane + 256];
            h3 = *(const float4*)&s_h[4 * lane + 384];
        } else {
            h0 = h1 = h2 = h3 = make_float4(0.f, 0.f, 0.f, 0.f);
        }

        // --- 5 dot products (this unit's i,o,f,u,r rows) ---
        float acc[5];
#pragma unroll
        for (int g = 0; g < 5; g++) {
            float a0 = fmaf(wv[g][0].x, h0.x, fmaf(wv[g][0].y, h0.y,
                       fmaf(wv[g][0].z, h0.z, wv[g][0].w * h0.w)));
            float a1 = fmaf(wv[g][1].x, h1.x, fmaf(wv[g][1].y, h1.y,
                       fmaf(wv[g][1].z, h1.z, wv[g][1].w * h1.w)));
            float a2 = fmaf(wv[g][2].x, h2.x, fmaf(wv[g][2].y, h2.y,
                       fmaf(wv[g][2].z, h2.z, wv[g][2].w * h2.w)));
            float a3 = fmaf(wv[g][3].x, h3.x, fmaf(wv[g][3].y, h3.y,
                       fmaf(wv[g][3].z, h3.z, wv[g][3].w * h3.w)));
            acc[g] = (a0 + a1) + (a2 + a3);
        }

        // --- fused 5-way butterfly reduce: ALL lanes end with the sums ---
#pragma unroll
        for (int off = 16; off; off >>= 1) {
#pragma unroll
            for (int g = 0; g < 5; g++)
                acc[g] += __shfl_xor_sync(0xffffffffu, acc[g], off);
        }

        // --- gate math on ALL lanes (redundant; enables direct fan-out) ---
        float cpar = 0.0f;
        if (p >= 0) {
            if (p == t - 1) {
                cpar = c_last;                           // chain fast path
            } else {
                const float* cp = &g_C[(size_t)p * HDIM + unit];
                do { cpar = ld_volatile_f(cp); }         // general tree
                while (__float_as_uint(cpar) == SENT);
            }
        }
        float iv = sigm(acc[0] + xg[0]);
        float ov = sigm(acc[1] + xg[1]);
        float fv = sigm(acc[2] + xg[2]);
        float uv = tanhfast(acc[3] + xg[3]);
        float rv = sigm(acc[4] + xg[4]);
        float c  = desent(fmaf(fv, cpar, iv * uv));
        float hh = ov * tanhfast(c);
        float hf = rv * hh + (1.0f - rv) * px;
        c_last = c;

        // --- publish: lanes 0..7 fan out {hf, t+1} to the 8 copies ---
        if (lane < NCOPIES)
            st_v2_u32(&g_mbox[t & 1][lane][unit],
                      __float_as_uint(hf), (unsigned)(t + 1));
        if (lane == 0) {
            Hout[(size_t)t * HDIM + unit] = hf;          // final output
            g_C[(size_t)t * HDIM + unit]  = c;           // general-tree state
        }

        // --- prefetch next node's static terms (all lanes, broadcast) ---
        if (t + 1 < NNODES) {
#pragma unroll
            for (int g = 0; g < 5; g++)
                xg[g] = g_xgb[(size_t)(t + 1) * GDIM + g * HDIM + unit];
            px = g_pxb[(size_t)(t + 1) * HDIM + unit];
        }

        // s_h reuse is globally gated on the chain (poll t+1 cannot succeed
        // before every warp published t); bar only needed for non-chain t+1.
        if (t + 1 < NNODES && p_next != t) __syncthreads();

        p = p_next;
    }
}

extern "C" void kernel_launch(void* const* d_in, const int* in_sizes, int n_in,
                              void* d_out, int out_size) {
    const float* features = (const float*)d_in[0];
    const int*   parents  = (const int*)d_in[1];
    const float* Wpx      = (const float*)d_in[2];
    const float* bpx      = (const float*)d_in[3];
    const float* Wx       = (const float*)d_in[4];
    const float* bx       = (const float*)d_in[5];
    const float* Wh       = (const float*)d_in[6];
    const float* bh       = (const float*)d_in[7];
    float* Hout = (float*)d_out;

    float* d_pxb = nullptr;
    float* d_xgb = nullptr;
    float* d_C   = nullptr;
    cudaGetSymbolAddress((void**)&d_pxb, g_pxb);
    cudaGetSymbolAddress((void**)&d_xgb, g_xgb);
    cudaGetSymbolAddress((void**)&d_C,   g_C);

    // 1) reset mailbox tags + sentinel-poison g_C (replay-safe)
    poison_kernel<<<(MBOX_U4 + GC_F4 + 255) / 256, 256>>>((float4*)d_C);

    // 2) batched x-side projections
    dim3 gpx(HDIM / 128, NNODES / 128);
    sgemm_bt_bias<<<gpx, 256>>>(features, Wpx, bpx, nullptr, d_pxb,
                                NNODES, HDIM, FEATD);
    dim3 gxg(GDIM / 128, NNODES / 128);
    sgemm_bt_bias<<<gxg, 256>>>(features, Wx, bx, bh, d_xgb,
                                NNODES, GDIM, FEATD);

    // 3) serial recurrence (tagged-mailbox dataflow, 64 co-resident CTAs)
    treelstm_seq_kernel<<<NCTA, NTHR>>>(Wh, parents, Hout);
}

// round 8
// speedup vs baseline: 1.0776x; 1.0776x over previous
#include <cuda_runtime.h>
#include <cstdint>

#define NNODES 8192
#define FEATD  1024
#define HDIM   512
#define GDIM   (5*HDIM)
#define NCTA   128
#define WPC    4                 // warps per CTA; warp w owns unit cta*4+w
#define NTHR   (WPC*32)
#define NCOPIES 16               // mailbox replicas; 8 consumer CTAs per copy
#define SENT   0xFFC0DEADu      // sentinel for g_C only (general-tree path)

// Scratch (static __device__ arrays: allocation-free per harness rules)
__device__ float g_xgb[(size_t)NNODES * GDIM];   // Wx·x + bx + bh   [N,5H]
__device__ float g_pxb[(size_t)NNODES * HDIM];   // Wpx·x + bpx      [N,H]
__device__ float g_C[(size_t)NNODES * HDIM];     // cell states      [N,H]
// Tagged mailbox: [step parity][copy][unit] = {h value bits, tag = t+1}
__device__ uint2 g_mbox[2][NCOPIES][HDIM];       // 128 KB

__device__ __forceinline__ float sigm(float x) {
    return 1.0f / (1.0f + __expf(-x));
}
__device__ __forceinline__ float tanhfast(float x) {
    return 1.0f - 2.0f / (__expf(2.0f * x) + 1.0f);
}
__device__ __forceinline__ uint4 ld_volatile_u4(const void* p) {
    uint4 v;
    asm volatile("ld.volatile.global.v4.b32 {%0,%1,%2,%3}, [%4];"
                 : "=r"(v.x), "=r"(v.y), "=r"(v.z), "=r"(v.w) : "l"(p) : "memory");
    return v;
}
__device__ __forceinline__ float ld_volatile_f(const float* p) {
    float v;
    asm volatile("ld.volatile.global.f32 %0, [%1];" : "=f"(v) : "l"(p) : "memory");
    return v;
}
__device__ __forceinline__ void st_v2_u32(void* p, unsigned a, unsigned b) {
    asm volatile("st.global.v2.b32 [%0], {%1,%2};" :: "l"(p), "r"(a), "r"(b) : "memory");
}
__device__ __forceinline__ float desent(float v) {   // g_C values only
    return (__float_as_uint(v) == SENT) ? __uint_as_float(SENT ^ 1u) : v;
}

// ---------------------------------------------------------------------------
// Per-launch reset: zero mailbox tags (128KB) + sentinel-poison g_C (16MB).
// ---------------------------------------------------------------------------
#define MBOX_U4   (int)(sizeof(g_mbox) / 16)      // 8192 uint4
#define GC_F4     (NNODES * HDIM / 4)             // 1048576 float4
__global__ void poison_kernel(float4* __restrict__ gc) {
    int i = blockIdx.x * blockDim.x + threadIdx.x;
    if (i < MBOX_U4) {
        ((uint4*)g_mbox)[i] = make_uint4(0u, 0u, 0u, 0u);
    }
    int j = i - MBOX_U4;
    if (j >= 0 && j < GC_F4) {
        float f = __uint_as_float(SENT);
        gc[j] = make_float4(f, f, f, f);
    }
}

// ---------------------------------------------------------------------------
// Batched precompute GEMM:  C[M,N] = A[M,K] * B[N,K]^T + b1[N] (+ b2[N])
// 128x128x8 SMEM-tiled fp32, 256 threads, 8x8 per-thread tile.
// ---------------------------------------------------------------------------
__global__ __launch_bounds__(256) void sgemm_bt_bias(
    const float* __restrict__ A, const float* __restrict__ B,
    const float* __restrict__ b1, const float* __restrict__ b2,
    float* __restrict__ C, int M, int N, int K)
{
    const int BM = 128, BN = 128;
    __shared__ float As[8][BM + 4];
    __shared__ float Bs[8][BN + 4];

    const int tid = threadIdx.x;
    const int bxi = blockIdx.x, byi = blockIdx.y;
    const int loadRow = tid >> 1;
    const int loadCol = (tid & 1) << 2;

    const float* Ab = A + (size_t)byi * BM * K;
    const float* Bb = B + (size_t)bxi * BN * K;

    const int ty = tid >> 4;
    const int tx = tid & 15;

    float acc[8][8];
#pragma unroll
    for (int i = 0; i < 8; i++)
#pragma unroll
        for (int j = 0; j < 8; j++) acc[i][j] = 0.0f;

    for (int k0 = 0; k0 < K; k0 += 8) {
        float4 av = *(const float4*)(Ab + (size_t)loadRow * K + k0 + loadCol);
        float4 bv = *(const float4*)(Bb + (size_t)loadRow * K + k0 + loadCol);
        As[loadCol + 0][loadRow] = av.x;
        As[loadCol + 1][loadRow] = av.y;
        As[loadCol + 2][loadRow] = av.z;
        As[loadCol + 3][loadRow] = av.w;
        Bs[loadCol + 0][loadRow] = bv.x;
        Bs[loadCol + 1][loadRow] = bv.y;
        Bs[loadCol + 2][loadRow] = bv.z;
        Bs[loadCol + 3][loadRow] = bv.w;
        __syncthreads();

#pragma unroll
        for (int k = 0; k < 8; k++) {
            float ar[8], br[8];
#pragma unroll
            for (int i = 0; i < 8; i++) ar[i] = As[k][ty * 8 + i];
#pragma unroll
            for (int j = 0; j < 8; j++) br[j] = Bs[k][tx * 8 + j];
#pragma unroll
            for (int i = 0; i < 8; i++)
#pragma unroll
                for (int j = 0; j < 8; j++)
                    acc[i][j] = fmaf(ar[i], br[j], acc[i][j]);
        }
        __syncthreads();
    }

#pragma unroll
    for (int i = 0; i < 8; i++) {
        int m = byi * BM + ty * 8 + i;
        int nbase = bxi * BN + tx * 8;
        float v[8];
#pragma unroll
        for (int j = 0; j < 8; j++) {
            v[j] = acc[i][j] + b1[nbase + j];
            if (b2) v[j] += b2[nbase + j];
        }
        float4* out = (float4*)(C + (size_t)m * N + nbase);
        out[0] = make_float4(v[0], v[1], v[2], v[3]);
        out[1] = make_float4(v[4], v[5], v[6], v[7]);
    }
}

// ---------------------------------------------------------------------------
// Persistent serial recurrence. 128 CTAs x 128 threads; warp w owns unit
// cta*4+w -> exactly ONE recurrence warp per SMSP (no issue-port contention
// on the dot/reduce). Tagged 16-copy mailbox keeps poll fan-in at 8
// readers/line. Polling is 2-deep pipelined (sampling ~ RT/2). All lanes do
// the gate math redundantly; lanes 0..15 fan {hf, t+1} out to the 16 copies.
// ---------------------------------------------------------------------------
__global__ __launch_bounds__(NTHR, 1) void treelstm_seq_kernel(
    const float* __restrict__ Wh, const int* __restrict__ parents,
    float* __restrict__ Hout)
{
    __shared__ float s_h[HDIM];      // assembled h[parent] (2KB)
    __shared__ int   s_par[NNODES];  // parents table (32KB, stays in SMEM)

    const int cta  = blockIdx.x;
    const int w    = threadIdx.x >> 5;
    const int lane = threadIdx.x & 31;
    const int unit = cta * WPC + w;
    const int copy = cta >> 3;       // 8 CTAs share a mailbox copy

    // Stage parents into SMEM (64 entries per thread)
    for (int i = threadIdx.x; i < NNODES; i += NTHR) s_par[i] = parents[i];

    // Pin this unit's 5 Wh rows in registers: lane covers k = 4*lane + 128*c.
    float4 wv[5][4];
#pragma unroll
    for (int g = 0; g < 5; g++) {
        const float* wrow = Wh + (size_t)(g * HDIM + unit) * HDIM + 4 * lane;
#pragma unroll
        for (int c = 0; c < 4; c++)
            wv[g][c] = *(const float4*)(wrow + 128 * c);
    }

    // Node-0 static terms (lane-uniform broadcast loads, all lanes)
    float xg[5], px;
#pragma unroll
    for (int g = 0; g < 5; g++) xg[g] = g_xgb[(size_t)(g * HDIM + unit)];
    px = g_pxb[unit];

    __syncthreads();                 // s_par ready
    float c_last = 0.0f;
    int p = s_par[0];

    for (int t = 0; t < NNODES; t++) {
        const int p_next = (t + 1 < NNODES) ? s_par[t + 1] : 0;

        float4 h0, h1, h2, h3;
        if (p >= 0) {
            // --- poll own copy, warp w covers units [128w, 128w+128) ------
            // 2-deep pipelined sampling: keep two tag-samples in flight.
            {
                const unsigned expect = (unsigned)(p + 1);
                const uint2* mp = &g_mbox[p & 1][copy][128 * w + 2 * lane];
                uint4 a0 = ld_volatile_u4(mp);
                uint4 a1 = ld_volatile_u4(mp + 64);
                uint4 r0, r1;
                for (;;) {
                    uint4 b0 = ld_volatile_u4(mp);
                    uint4 b1 = ld_volatile_u4(mp + 64);
                    bool okA = (a0.y == expect) & (a0.w == expect) &
                               (a1.y == expect) & (a1.w == expect);
                    if (__all_sync(0xffffffffu, okA)) { r0 = a0; r1 = a1; break; }
                    uint4 c0 = ld_volatile_u4(mp);
                    uint4 c1 = ld_volatile_u4(mp + 64);
                    bool okB = (b0.y == expect) & (b0.w == expect) &
                               (b1.y == expect) & (b1.w == expect);
                    if (__all_sync(0xffffffffu, okB)) { r0 = b0; r1 = b1; break; }
                    a0 = c0; a1 = c1;
                }
                *(float2*)&s_h[128 * w + 2 * lane] =
                    make_float2(__uint_as_float(r0.x), __uint_as_float(r0.z));
                *(float2*)&s_h[128 * w + 64 + 2 * lane] =
                    make_float2(__uint_as_float(r1.x), __uint_as_float(r1.z));
            }
            __syncthreads();                   // s_h fully assembled
            h0 = *(const float4*)&s_h[4 * lane +   0];
            h1 = *(const float4*)&s_h[4 * lane + 128];
            h2 = *(const float4*)&s_h[4 * lane + 256];
            h3 = *(const float4*)&s_h[4 * lane + 384];
        } else {
            h0 = h1 = h2 = h3 = make_float4(0.f, 0.f, 0.f, 0.f);
        }

        // --- 5 dot products (this unit's i,o,f,u,r rows) ---
        float acc[5];
#pragma unroll
        for (int g = 0; g < 5; g++) {
            float a0 = fmaf(wv[g][0].x, h0.x, fmaf(wv[g][0].y, h0.y,
                       fmaf(wv[g][0].z, h0.z, wv[g][0].w * h0.w)));
            float a1 = fmaf(wv[g][1].x, h1.x, fmaf(wv[g][1].y, h1.y,
                       fmaf(wv[g][1].z, h1.z, wv[g][1].w * h1.w)));
            float a2 = fmaf(wv[g][2].x, h2.x, fmaf(wv[g][2].y, h2.y,
                       fmaf(wv[g][2].z, h2.z, wv[g][2].w * h2.w)));
            float a3 = fmaf(wv[g][3].x, h3.x, fmaf(wv[g][3].y, h3.y,
                       fmaf(wv[g][3].z, h3.z, wv[g][3].w * h3.w)));
            acc[g] = (a0 + a1) + (a2 + a3);
        }

        // --- fused 5-way butterfly reduce: ALL lanes end with the sums ---
#pragma unroll
        for (int off = 16; off; off >>= 1) {
#pragma unroll
            for (int g = 0; g < 5; g++)
                acc[g] += __shfl_xor_sync(0xffffffffu, acc[g], off);
        }

        // --- gate math on ALL lanes (redundant; enables 16-way fan-out) ---
        float cpar = 0.0f;
        if (p >= 0) {
            if (p == t - 1) {
                cpar = c_last;                           // chain fast path
            } else {
                const float* cp = &g_C[(size_t)p * HDIM + unit];
                do { cpar = ld_volatile_f(cp); }         // general tree
                while (__float_as_uint(cpar) == SENT);
            }
        }
        float iv = sigm(acc[0] + xg[0]);
        float ov = sigm(acc[1] + xg[1]);
        float fv = sigm(acc[2] + xg[2]);
        float uv = tanhfast(acc[3] + xg[3]);
        float rv = sigm(acc[4] + xg[4]);
        float c  = desent(fmaf(fv, cpar, iv * uv));
        float hh = ov * tanhfast(c);
        float hf = rv * hh + (1.0f - rv) * px;
        c_last = c;

        // --- publish: lanes 0..15 fan {hf, t+1} out to the 16 copies ---
        if (lane < NCOPIES)
            st_v2_u32(&g_mbox[t & 1][lane][unit],
                      __float_as_uint(hf), (unsigned)(t + 1));
        if (lane == 0) {
            Hout[(size_t)t * HDIM + unit] = hf;          // final output
            g_C[(size_t)t * HDIM + unit]  = c;           // general-tree state
        }

        // --- prefetch next node's static terms (broadcast, off-path) ---
        if (t + 1 < NNODES) {
#pragma unroll
            for (int g = 0; g < 5; g++)
                xg[g] = g_xgb[(size_t)(t + 1) * GDIM + g * HDIM + unit];
            px = g_pxb[(size_t)(t + 1) * HDIM + unit];
        }

        // s_h reuse is globally gated on the chain (poll t+1 cannot succeed
        // before every warp published t); bar only needed for non-chain t+1.
        if (t + 1 < NNODES && p_next != t) __syncthreads();

        p = p_next;
    }
}

extern "C" void kernel_launch(void* const* d_in, const int* in_sizes, int n_in,
                              void* d_out, int out_size) {
    const float* features = (const float*)d_in[0];
    const int*   parents  = (const int*)d_in[1];
    const float* Wpx      = (const float*)d_in[2];
    const float* bpx      = (const float*)d_in[3];
    const float* Wx       = (const float*)d_in[4];
    const float* bx       = (const float*)d_in[5];
    const float* Wh       = (const float*)d_in[6];
    const float* bh       = (const float*)d_in[7];
    float* Hout = (float*)d_out;

    float* d_pxb = nullptr;
    float* d_xgb = nullptr;
    float* d_C   = nullptr;
    cudaGetSymbolAddress((void**)&d_pxb, g_pxb);
    cudaGetSymbolAddress((void**)&d_xgb, g_xgb);
    cudaGetSymbolAddress((void**)&d_C,   g_C);

    // 1) reset mailbox tags + sentinel-poison g_C (replay-safe)
    poison_kernel<<<(MBOX_U4 + GC_F4 + 255) / 256, 256>>>((float4*)d_C);

    // 2) batched x-side projections
    dim3 gpx(HDIM / 128, NNODES / 128);
    sgemm_bt_bias<<<gpx, 256>>>(features, Wpx, bpx, nullptr, d_pxb,
                                NNODES, HDIM, FEATD);
    dim3 gxg(GDIM / 128, NNODES / 128);
    sgemm_bt_bias<<<gxg, 256>>>(features, Wx, bx, bh, d_xgb,
                                NNODES, GDIM, FEATD);

    // 3) serial recurrence (tagged-mailbox dataflow, 128 co-resident CTAs,
    //    one recurrence warp per SMSP)
    treelstm_seq_kernel<<<NCTA, NTHR>>>(Wh, parents, Hout);
}